// round 5
// baseline (speedup 1.0000x reference)
#include <cuda_runtime.h>

// metaCLF fused kernel, R3: packed fp32x2 math + 128-bit shared weight loads.
//
// R2 post-mortem showed the kernel LSU-bound (L1TEX 72.8%, fma 37%): one
// LDS.64 per FFMA2. This round every weight fetch is ld.shared.v2.b64
// (one LDS.128 feeds two FFMA2s), with padded/transposed smem layouts:
//   sW1  [32]        pairs (2j,2j+1) -> v2
//   sW2t [16][4]     transposed+padded W2 -> v2 + scalar
//   sG1p [32][28]    rows padded 27->28 -> 14 v2/row (enc28[27]=0)
//   sG2  [64][32]    already row-contiguous -> 16 v2/row
//   sG3t [64][32]    transposed G3 -> 16 v2/row
// __launch_bounds__(128,3) caps regs for 3 blocks/SM (12 warps).

typedef unsigned long long u64;

#define HWD   (96*96*96)   // 884736
#define NPAIR (HWD/2)      // 442368
#define NB    2

// smem layout offsets (in u64 units)
#define OFF_W1   0
#define OFF_W2T  32
#define OFF_G1P  96
#define OFF_G2   992
#define OFF_G3T  3040
#define SW_TOTAL 5088

__device__ __forceinline__ u64 bc2(float w) {
    u64 r; asm("mov.b64 %0, {%1, %2};" : "=l"(r) : "f"(w), "f"(w)); return r;
}
__device__ __forceinline__ u64 fma2(u64 a, u64 b, u64 c) {
    u64 d; asm("fma.rn.f32x2 %0, %1, %2, %3;" : "=l"(d) : "l"(a), "l"(b), "l"(c)); return d;
}
__device__ __forceinline__ u64 mul2(u64 a, u64 b) {
    u64 d; asm("mul.rn.f32x2 %0, %1, %2;" : "=l"(d) : "l"(a), "l"(b)); return d;
}
__device__ __forceinline__ u64 add2(u64 a, u64 b) {
    u64 d; asm("add.rn.f32x2 %0, %1, %2;" : "=l"(d) : "l"(a), "l"(b)); return d;
}
__device__ __forceinline__ u64 relu2(u64 a) {
    float lo, hi;
    asm("mov.b64 {%0, %1}, %2;" : "=f"(lo), "=f"(hi) : "l"(a));
    lo = fmaxf(lo, 0.0f); hi = fmaxf(hi, 0.0f);
    u64 r; asm("mov.b64 %0, {%1, %2};" : "=l"(r) : "f"(lo), "f"(hi));
    return r;
}
// 128-bit shared load: one LDS.128 returning two packed weights.
__device__ __forceinline__ void lds2(const u64* p, u64& a, u64& b) {
    unsigned long long sp = __cvta_generic_to_shared(p);
    asm("ld.shared.v2.b64 {%0, %1}, [%2];" : "=l"(a), "=l"(b) : "l"(sp));
}

__global__ void __launch_bounds__(128, 3)
metaCLF_kernel(const float* __restrict__ x, const float* __restrict__ d_all,
               const float* __restrict__ W1, const float* __restrict__ W2,
               const float* __restrict__ G1, const float* __restrict__ G2,
               const float* __restrict__ G3, float* __restrict__ out)
{
    __shared__ __align__(16) u64 sw[SW_TOTAL];
    {
        const int t = threadIdx.x;
        for (int i = t; i < 32; i += 128) sw[OFF_W1 + i] = bc2(W1[i]);
        for (int i = t; i < 64; i += 128) {
            int j = i >> 2, o = i & 3;
            sw[OFF_W2T + i] = (o < 3) ? bc2(W2[o * 16 + j]) : 0ull;
        }
        for (int i = t; i < 896; i += 128) {
            int c = i / 28, e = i - c * 28;
            sw[OFF_G1P + i] = (e < 27) ? bc2(G1[c * 27 + e]) : 0ull;
        }
        for (int i = t; i < 2048; i += 128) sw[OFF_G2 + i] = bc2(G2[i]);
        for (int i = t; i < 2048; i += 128) {
            int k = i >> 5, c = i & 31;
            sw[OFF_G3T + i] = bc2(G3[c * 64 + k]);
        }
    }
    __syncthreads();
    const u64* sW1  = sw + OFF_W1;
    const u64* sW2t = sw + OFF_W2T;
    const u64* sG1p = sw + OFF_G1P;
    const u64* sG2  = sw + OFF_G2;
    const u64* sG3t = sw + OFF_G3T;

    const int g = blockIdx.x * 128 + threadIdx.x;   // pair index, exact grid
    const int b = g / NPAIR;
    const long long v = (long long)(g - b * NPAIR) * 2;

    // ---- encode: e[axis][o] = W2 @ relu(W1 @ d_pair) ----
    const float* db = d_all + (long long)b * 6 * HWD + v;
    u64 e[3][3];
#pragma unroll
    for (int a = 0; a < 3; ++a) {
        const u64 d0 = *(const u64*)(db + (long long)(2 * a + 0) * HWD);
        const u64 d1 = *(const u64*)(db + (long long)(2 * a + 1) * HWD);
        u64 a0, a1, a2;
#pragma unroll
        for (int j = 0; j < 16; ++j) {
            u64 w10, w11;
            lds2(sW1 + 2 * j, w10, w11);               // W1[j][0], W1[j][1]
            u64 t = fma2(w10, d0, mul2(w11, d1));
            t = relu2(t);
            u64 w20, w21;
            lds2(sW2t + 4 * j, w20, w21);              // W2[0][j], W2[1][j]
            const u64 w22 = sW2t[4 * j + 2];           // W2[2][j]
            if (j == 0) {
                a0 = mul2(w20, t);
                a1 = mul2(w21, t);
                a2 = mul2(w22, t);
            } else {
                a0 = fma2(w20, t, a0);
                a1 = fma2(w21, t, a1);
                a2 = fma2(w22, t, a2);
            }
        }
        e[a][0] = a0; e[a][1] = a1; e[a][2] = a2;
    }

    // ---- kron -> enc28 (padded with zero at [27]) ----
    u64 enc28[28];
#pragma unroll
    for (int i = 0; i < 3; ++i)
#pragma unroll
        for (int j = 0; j < 3; ++j) {
            const u64 pij = mul2(e[0][i], e[1][j]);
#pragma unroll
            for (int k = 0; k < 3; ++k)
                enc28[(i * 3 + j) * 3 + k] = mul2(pij, e[2][k]);
        }
    enc28[27] = 0ull;

    // ---- h = relu(G1 @ enc), row-contiguous v2 loads ----
    u64 h[32];
#pragma unroll 4
    for (int c = 0; c < 32; ++c) {
        const u64* row = sG1p + c * 28;
        u64 w0, w1;
        lds2(row, w0, w1);
        u64 a0 = mul2(w0, enc28[0]);
        u64 a1 = mul2(w1, enc28[1]);
#pragma unroll
        for (int eI = 2; eI < 28; eI += 2) {
            lds2(row + eI, w0, w1);
            a0 = fma2(w0, enc28[eI],     a0);
            a1 = fma2(w1, enc28[eI + 1], a1);
        }
        h[c] = relu2(add2(a0, a1));
    }

    // ---- load x (packed pair per channel) ----
    const float* xb = x + (long long)b * 32 * HWD + v;
    u64 xr[32];
#pragma unroll
    for (int c = 0; c < 32; ++c)
        xr[c] = *(const u64*)(xb + (long long)c * HWD);

    // ---- out = sum_k relu(G2[k,:]@h) * (G3t[k,:] . x) ----
    u64 acc = 0ull;
#pragma unroll 2
    for (int k = 0; k < 64; ++k) {
        const u64* g2 = sG2  + k * 32;
        const u64* g3 = sG3t + k * 32;
        u64 w0, w1, u0, u1;
        lds2(g2, w0, w1);
        lds2(g3, u0, u1);
        u64 s0 = mul2(w0, h[0]);
        u64 s1 = mul2(w1, h[1]);
        u64 t0 = mul2(u0, xr[0]);
        u64 t1 = mul2(u1, xr[1]);
#pragma unroll
        for (int c = 2; c < 32; c += 2) {
            lds2(g2 + c, w0, w1);
            s0 = fma2(w0, h[c],     s0);
            s1 = fma2(w1, h[c + 1], s1);
            lds2(g3 + c, u0, u1);
            t0 = fma2(u0, xr[c],     t0);
            t1 = fma2(u1, xr[c + 1], t1);
        }
        const u64 hk = relu2(add2(s0, s1));
        acc = fma2(hk, add2(t0, t1), acc);
    }

    *(u64*)(out + (long long)b * HWD + v) = acc;
}

extern "C" void kernel_launch(void* const* d_in, const int* in_sizes, int n_in,
                              void* d_out, int out_size)
{
    const float* x    = (const float*)d_in[0];
    const float* dall = (const float*)d_in[1];
    const float* W1   = (const float*)d_in[2];
    const float* W2   = (const float*)d_in[3];
    const float* G1   = (const float*)d_in[4];
    const float* G2   = (const float*)d_in[5];
    const float* G3   = (const float*)d_in[6];
    float* out = (float*)d_out;

    const int total_threads = NB * NPAIR;          // 884736, divisible by 128
    dim3 grid(total_threads / 128);
    metaCLF_kernel<<<grid, 128>>>(x, dall, W1, W2, G1, G2, G3, out);
}

// round 6
// speedup vs baseline: 1.3482x; 1.3482x over previous
#include <cuda_runtime.h>

// metaCLF R5: V=2 register blocking (4 voxels/thread) + 2-kernel split.
//
// R3 post-mortem: bound by smem wavefronts (1 per weight, = 1 per FMA).
// Fix: amortize each weight load over two packed voxel-pairs (ratio 0.25).
// Register wall broken by splitting:
//   Kernel Y: y[b][k][vox] = G3^T x      (xr resident only)
//   Kernel F: encode->kron->G1->G2 fused with out = sum_k relu(s_k) * y_k
//             (h resident only; kron factors recomputed e-major in G1)

typedef unsigned long long u64;

#define HWD   (96*96*96)   // 884736
#define NQUAD (HWD/4)      // 221184 quads (4 voxels) per batch
#define NB    2

// 453MB scratch for y = G3^T x  (allowed: static __device__ array)
__device__ float y_buf[(long long)NB * 64 * HWD];

__device__ __forceinline__ u64 bc2(float w) {
    u64 r; asm("mov.b64 %0, {%1, %2};" : "=l"(r) : "f"(w), "f"(w)); return r;
}
__device__ __forceinline__ u64 fma2(u64 a, u64 b, u64 c) {
    u64 d; asm("fma.rn.f32x2 %0, %1, %2, %3;" : "=l"(d) : "l"(a), "l"(b), "l"(c)); return d;
}
__device__ __forceinline__ u64 mul2(u64 a, u64 b) {
    u64 d; asm("mul.rn.f32x2 %0, %1, %2;" : "=l"(d) : "l"(a), "l"(b)); return d;
}
__device__ __forceinline__ u64 add2(u64 a, u64 b) {
    u64 d; asm("add.rn.f32x2 %0, %1, %2;" : "=l"(d) : "l"(a), "l"(b)); return d;
}
__device__ __forceinline__ u64 relu2(u64 a) {
    float lo, hi;
    asm("mov.b64 {%0, %1}, %2;" : "=f"(lo), "=f"(hi) : "l"(a));
    lo = fmaxf(lo, 0.0f); hi = fmaxf(hi, 0.0f);
    u64 r; asm("mov.b64 %0, {%1, %2};" : "=l"(r) : "f"(lo), "f"(hi));
    return r;
}
__device__ __forceinline__ void lds2(const u64* p, u64& a, u64& b) {
    unsigned long long sp = __cvta_generic_to_shared(p);
    asm("ld.shared.v2.b64 {%0, %1}, [%2];" : "=l"(a), "=l"(b) : "l"(sp));
}

// ===================== Kernel Y: y = G3^T x =====================
__global__ void __launch_bounds__(128)
y_kernel(const float* __restrict__ x, const float* __restrict__ G3)
{
    __shared__ __align__(16) u64 sG3t[2048];   // [k][c] packed {w,w}
    for (int i = threadIdx.x; i < 2048; i += 128) {
        int k = i >> 5, c = i & 31;
        sG3t[i] = bc2(G3[c * 64 + k]);
    }
    __syncthreads();

    const int q = blockIdx.x * 128 + threadIdx.x;    // quad index (exact grid)
    const int b = q / NQUAD;
    const long long v = (long long)(q - b * NQUAD) * 4;

    const float* xb = x + (long long)b * 32 * HWD + v;
    u64 xA[32], xB[32];
#pragma unroll
    for (int c = 0; c < 32; ++c) {
        ulonglong2 p = *(const ulonglong2*)(xb + (long long)c * HWD);
        xA[c] = p.x; xB[c] = p.y;
    }

    float* yb = y_buf + (long long)b * 64 * HWD + v;
#pragma unroll 4
    for (int k = 0; k < 64; ++k) {
        const u64* row = sG3t + k * 32;
        u64 sA0 = 0, sA1 = 0, sB0 = 0, sB1 = 0;
#pragma unroll
        for (int c = 0; c < 32; c += 2) {
            u64 w0, w1; lds2(row + c, w0, w1);
            sA0 = fma2(w0, xA[c],     sA0);
            sB0 = fma2(w0, xB[c],     sB0);
            sA1 = fma2(w1, xA[c + 1], sA1);
            sB1 = fma2(w1, xB[c + 1], sB1);
        }
        ulonglong2 o; o.x = add2(sA0, sA1); o.y = add2(sB0, sB1);
        *(ulonglong2*)(yb + (long long)k * HWD) = o;
    }
}

// ============ Kernel F: encode->G1->G2 + fused dot with y ============
// smem layout (u64 units): W1 @0 [32], W2T @32 [64], G1T @96 [27*32], G2 @960 [64*32]
#define FOFF_W1   0
#define FOFF_W2T  32
#define FOFF_G1T  96
#define FOFF_G2   960
#define FSW_TOT   3008

__global__ void __launch_bounds__(128, 2)
f_kernel(const float* __restrict__ d_all,
         const float* __restrict__ W1, const float* __restrict__ W2,
         const float* __restrict__ G1, const float* __restrict__ G2,
         float* __restrict__ out)
{
    __shared__ __align__(16) u64 sw[FSW_TOT];
    {
        const int t = threadIdx.x;
        for (int i = t; i < 32; i += 128) sw[FOFF_W1 + i] = bc2(W1[i]);
        for (int i = t; i < 64; i += 128) {
            int j = i >> 2, o = i & 3;
            sw[FOFF_W2T + i] = (o < 3) ? bc2(W2[o * 16 + j]) : 0ull;
        }
        for (int i = t; i < 864; i += 128) {
            int e = i >> 5, c = i & 31;                 // G1T [e][c]
            sw[FOFF_G1T + i] = bc2(G1[c * 27 + e]);
        }
        for (int i = t; i < 2048; i += 128) sw[FOFF_G2 + i] = bc2(G2[i]);
    }
    __syncthreads();
    const u64* sW1  = sw + FOFF_W1;
    const u64* sW2t = sw + FOFF_W2T;
    const u64* sG1t = sw + FOFF_G1T;
    const u64* sG2  = sw + FOFF_G2;

    const int q = blockIdx.x * 128 + threadIdx.x;
    const int b = q / NQUAD;
    const long long v = (long long)(q - b * NQUAD) * 4;

    // ---- encode both pairs (weights shared) ----
    const float* db = d_all + (long long)b * 6 * HWD + v;
    u64 pA[9], pB[9], e2A[3], e2B[3];
    {
        u64 eA[3][3], eB[3][3];
#pragma unroll
        for (int a = 0; a < 3; ++a) {
            ulonglong2 r0 = *(const ulonglong2*)(db + (long long)(2 * a + 0) * HWD);
            ulonglong2 r1 = *(const ulonglong2*)(db + (long long)(2 * a + 1) * HWD);
            const u64 dA0 = r0.x, dB0 = r0.y, dA1 = r1.x, dB1 = r1.y;
            u64 aA0 = 0, aA1 = 0, aA2 = 0, aB0 = 0, aB1 = 0, aB2 = 0;
#pragma unroll
            for (int j = 0; j < 16; ++j) {
                u64 w10, w11; lds2(sW1 + 2 * j, w10, w11);
                u64 tA = relu2(fma2(w10, dA0, mul2(w11, dA1)));
                u64 tB = relu2(fma2(w10, dB0, mul2(w11, dB1)));
                u64 w20, w21; lds2(sW2t + 4 * j, w20, w21);
                const u64 w22 = sW2t[4 * j + 2];
                aA0 = fma2(w20, tA, aA0);  aB0 = fma2(w20, tB, aB0);
                aA1 = fma2(w21, tA, aA1);  aB1 = fma2(w21, tB, aB1);
                aA2 = fma2(w22, tA, aA2);  aB2 = fma2(w22, tB, aB2);
            }
            eA[a][0] = aA0; eA[a][1] = aA1; eA[a][2] = aA2;
            eB[a][0] = aB0; eB[a][1] = aB1; eB[a][2] = aB2;
        }
        // kron partials: p[i*3+j] = e_x[i]*e_y[j];  e2 = e_z
#pragma unroll
        for (int i = 0; i < 3; ++i)
#pragma unroll
            for (int j = 0; j < 3; ++j) {
                pA[i * 3 + j] = mul2(eA[0][i], eA[1][j]);
                pB[i * 3 + j] = mul2(eB[0][i], eB[1][j]);
            }
#pragma unroll
        for (int k = 0; k < 3; ++k) { e2A[k] = eA[2][k]; e2B[k] = eB[2][k]; }
    }

    // ---- G1, e-major (enc recomputed per e; weights shared over pairs) ----
    u64 hA[32], hB[32];
#pragma unroll
    for (int c = 0; c < 32; ++c) { hA[c] = 0ull; hB[c] = 0ull; }
#pragma unroll 3
    for (int ij = 0; ij < 9; ++ij) {
#pragma unroll
        for (int kk = 0; kk < 3; ++kk) {
            const u64 encA = mul2(pA[ij], e2A[kk]);
            const u64 encB = mul2(pB[ij], e2B[kk]);
            const u64* row = sG1t + (ij * 3 + kk) * 32;
#pragma unroll
            for (int c = 0; c < 32; c += 2) {
                u64 w0, w1; lds2(row + c, w0, w1);
                hA[c]     = fma2(w0, encA, hA[c]);
                hB[c]     = fma2(w0, encB, hB[c]);
                hA[c + 1] = fma2(w1, encA, hA[c + 1]);
                hB[c + 1] = fma2(w1, encB, hB[c + 1]);
            }
        }
    }
#pragma unroll
    for (int c = 0; c < 32; ++c) { hA[c] = relu2(hA[c]); hB[c] = relu2(hB[c]); }

    // ---- k-loop: out += relu(G2[k]·h) * y_k ----
    const float* yb = y_buf + (long long)b * 64 * HWD + v;
    u64 accA = 0ull, accB = 0ull;
#pragma unroll 4
    for (int k = 0; k < 64; ++k) {
        const u64* row = sG2 + k * 32;
        u64 sA0 = 0, sA1 = 0, sB0 = 0, sB1 = 0;
#pragma unroll
        for (int c = 0; c < 32; c += 2) {
            u64 w0, w1; lds2(row + c, w0, w1);
            sA0 = fma2(w0, hA[c],     sA0);
            sB0 = fma2(w0, hB[c],     sB0);
            sA1 = fma2(w1, hA[c + 1], sA1);
            sB1 = fma2(w1, hB[c + 1], sB1);
        }
        const u64 hkA = relu2(add2(sA0, sA1));
        const u64 hkB = relu2(add2(sB0, sB1));
        ulonglong2 y2 = *(const ulonglong2*)(yb + (long long)k * HWD);
        accA = fma2(hkA, y2.x, accA);
        accB = fma2(hkB, y2.y, accB);
    }

    ulonglong2 o; o.x = accA; o.y = accB;
    *(ulonglong2*)(out + (long long)b * HWD + v) = o;
}

extern "C" void kernel_launch(void* const* d_in, const int* in_sizes, int n_in,
                              void* d_out, int out_size)
{
    const float* x    = (const float*)d_in[0];
    const float* dall = (const float*)d_in[1];
    const float* W1   = (const float*)d_in[2];
    const float* W2   = (const float*)d_in[3];
    const float* G1   = (const float*)d_in[4];
    const float* G2   = (const float*)d_in[5];
    const float* G3   = (const float*)d_in[6];
    float* out = (float*)d_out;

    const int total_threads = NB * NQUAD;      // 442368 = 3456 * 128
    dim3 grid(total_threads / 128);
    y_kernel<<<grid, 128>>>(x, G3);
    f_kernel<<<grid, 128>>>(dall, W1, W2, G1, G2, out);
}